// round 1
// baseline (speedup 1.0000x reference)
#include <cuda_runtime.h>

#define DIM   1536
#define NH    24
#define HD    64
#define S_IMG 2048
#define T_TXT 512
#define LTOT  2560

// Scratch (device globals: no allocation allowed)
__device__ float g_q[LTOT * DIM];
__device__ float g_k[LTOT * DIM];
__device__ float g_v[LTOT * DIM];
__device__ float g_o[LTOT * DIM];

// ---------------------------------------------------------------------------
// GEMM: Y[m][n] = sum_d X[m][d] * W[n][d] + bias[n]   (i.e. X @ W^T + b)
// BM=128, BN=64, BK=16, 256 threads, 8x4 per-thread micro-tile.
// M must be a multiple of 128; N=K=1536.
// ---------------------------------------------------------------------------
__global__ __launch_bounds__(256) void gemm_bias(
    const float* __restrict__ X, const float* __restrict__ W,
    const float* __restrict__ bias, float* __restrict__ Y)
{
    __shared__ float As[16][132];
    __shared__ float Bs[16][68];
    const int row0 = blockIdx.y * 128;
    const int col0 = blockIdx.x * 64;
    const int tid = threadIdx.x;
    const int ty = tid >> 4, tx = tid & 15;
    const int am = tid >> 2;          // 0..63
    const int ak = (tid & 3) << 2;    // 0,4,8,12

    const float* Xa = X + (size_t)(row0 + am) * DIM + ak;
    const float* Xb = X + (size_t)(row0 + am + 64) * DIM + ak;
    const float* Wp = W + (size_t)(col0 + am) * DIM + ak;

    float acc[8][4];
    #pragma unroll
    for (int i = 0; i < 8; i++)
        #pragma unroll
        for (int j = 0; j < 4; j++) acc[i][j] = 0.f;

    for (int k0 = 0; k0 < DIM; k0 += 16) {
        float4 a0 = *(const float4*)(Xa + k0);
        float4 a1 = *(const float4*)(Xb + k0);
        float4 b0 = *(const float4*)(Wp + k0);
        __syncthreads();
        As[ak + 0][am] = a0.x; As[ak + 1][am] = a0.y;
        As[ak + 2][am] = a0.z; As[ak + 3][am] = a0.w;
        As[ak + 0][am + 64] = a1.x; As[ak + 1][am + 64] = a1.y;
        As[ak + 2][am + 64] = a1.z; As[ak + 3][am + 64] = a1.w;
        Bs[ak + 0][am] = b0.x; Bs[ak + 1][am] = b0.y;
        Bs[ak + 2][am] = b0.z; Bs[ak + 3][am] = b0.w;
        __syncthreads();
        #pragma unroll
        for (int kk = 0; kk < 16; kk++) {
            float a[8], b[4];
            #pragma unroll
            for (int i = 0; i < 8; i++) a[i] = As[kk][ty * 8 + i];
            #pragma unroll
            for (int j = 0; j < 4; j++) b[j] = Bs[kk][tx * 4 + j];
            #pragma unroll
            for (int i = 0; i < 8; i++)
                #pragma unroll
                for (int j = 0; j < 4; j++)
                    acc[i][j] = fmaf(a[i], b[j], acc[i][j]);
        }
    }
    #pragma unroll
    for (int j = 0; j < 4; j++) {
        float bj = bias[col0 + tx * 4 + j];
        #pragma unroll
        for (int i = 0; i < 8; i++)
            Y[(size_t)(row0 + ty * 8 + i) * DIM + col0 + tx * 4 + j] = acc[i][j] + bj;
    }
}

// ---------------------------------------------------------------------------
// Per-head LayerNorm (affine weight only) over HD=64, in-place on q_cat & k_cat.
// One warp per (row, head). blockIdx.y: 0 -> q tensor, 1 -> k tensor.
// ---------------------------------------------------------------------------
__global__ __launch_bounds__(256) void ln_heads(
    float* __restrict__ qb, float* __restrict__ kb,
    const float* __restrict__ gq, const float* __restrict__ gk,
    const float* __restrict__ gaq, const float* __restrict__ gak)
{
    int gw = blockIdx.x * 8 + (threadIdx.x >> 5);
    int lane = threadIdx.x & 31;
    int row = gw / NH;
    int h = gw - row * NH;
    float* base = blockIdx.y ? kb : qb;
    const float* g;
    if (blockIdx.y == 0) g = (row < S_IMG) ? gq : gaq;
    else                 g = (row < S_IMG) ? gk : gak;

    float* p = base + (size_t)row * DIM + h * HD;
    float x0 = p[lane], x1 = p[lane + 32];
    float s = x0 + x1, s2 = x0 * x0 + x1 * x1;
    #pragma unroll
    for (int m = 16; m; m >>= 1) {
        s  += __shfl_xor_sync(0xffffffffu, s, m);
        s2 += __shfl_xor_sync(0xffffffffu, s2, m);
    }
    float mean = s * (1.f / HD);
    float var  = s2 * (1.f / HD) - mean * mean;
    float inv  = rsqrtf(var + 1e-5f);
    p[lane]      = (x0 - mean) * inv * g[lane];
    p[lane + 32] = (x1 - mean) * inv * g[lane + 32];
}

// ---------------------------------------------------------------------------
// Flash attention, fp32, per head. BQ=128 query rows per block, BK=64 keys per
// inner step, online softmax. 256 threads; each thread owns 8 q-rows x 4 dims.
// ---------------------------------------------------------------------------
#define BQ 128
#define BK 64
#define SMEM_ATTN ((2 * 128 * 65 + 2 * 64 * 65) * 4)  // 99840 bytes

__global__ __launch_bounds__(256) void attn_kernel(
    const float* __restrict__ Q, const float* __restrict__ K,
    const float* __restrict__ V, float* __restrict__ O)
{
    extern __shared__ float sm[];
    float (*Qs)[65] = (float (*)[65])sm;                  // [128][65]  q-major
    float (*Ps)[65] = (float (*)[65])(sm + 128 * 65);     // [128][65]  q-major
    float (*Kt)[65] = (float (*)[65])(sm + 256 * 65);     // [64][65]   d-major (transposed)
    float (*Vs)[65] = (float (*)[65])(sm + 320 * 65);     // [64][65]   k-major

    const int h  = blockIdx.y;
    const int q0 = blockIdx.x * BQ;
    const int tid = threadIdx.x;
    const int ty = tid >> 4, tx = tid & 15;
    const int dg = (tid & 15) << 2;   // 0,4,...,60
    const int lr = tid >> 4;          // 0..15

    for (int r = lr; r < BQ; r += 16) {
        float4 v4 = *(const float4*)(Q + (size_t)(q0 + r) * DIM + h * HD + dg);
        Qs[r][dg] = v4.x; Qs[r][dg + 1] = v4.y; Qs[r][dg + 2] = v4.z; Qs[r][dg + 3] = v4.w;
    }

    float m_i[8], l_i[8], acc[8][4];
    #pragma unroll
    for (int i = 0; i < 8; i++) {
        m_i[i] = -1e30f; l_i[i] = 0.f;
        #pragma unroll
        for (int j = 0; j < 4; j++) acc[i][j] = 0.f;
    }
    __syncthreads();

    for (int k0 = 0; k0 < LTOT; k0 += BK) {
        for (int r = lr; r < BK; r += 16) {
            float4 kv = *(const float4*)(K + (size_t)(k0 + r) * DIM + h * HD + dg);
            Kt[dg][r] = kv.x; Kt[dg + 1][r] = kv.y; Kt[dg + 2][r] = kv.z; Kt[dg + 3][r] = kv.w;
            float4 vv = *(const float4*)(V + (size_t)(k0 + r) * DIM + h * HD + dg);
            Vs[r][dg] = vv.x; Vs[r][dg + 1] = vv.y; Vs[r][dg + 2] = vv.z; Vs[r][dg + 3] = vv.w;
        }
        __syncthreads();

        // S = Q K^T for this tile (8x4 per thread)
        float s[8][4];
        #pragma unroll
        for (int i = 0; i < 8; i++)
            #pragma unroll
            for (int j = 0; j < 4; j++) s[i][j] = 0.f;

        for (int d = 0; d < HD; d++) {
            float a[8], b[4];
            #pragma unroll
            for (int i = 0; i < 8; i++) a[i] = Qs[ty * 8 + i][d];
            #pragma unroll
            for (int j = 0; j < 4; j++) b[j] = Kt[d][tx * 4 + j];
            #pragma unroll
            for (int i = 0; i < 8; i++)
                #pragma unroll
                for (int j = 0; j < 4; j++)
                    s[i][j] = fmaf(a[i], b[j], s[i][j]);
        }

        // Online softmax update (row stats reduced across the 16-thread row group)
        #pragma unroll
        for (int i = 0; i < 8; i++) {
            float tm = -1e30f;
            #pragma unroll
            for (int j = 0; j < 4; j++) { s[i][j] *= 0.125f; tm = fmaxf(tm, s[i][j]); }
            #pragma unroll
            for (int mk = 8; mk; mk >>= 1)
                tm = fmaxf(tm, __shfl_xor_sync(0xffffffffu, tm, mk));
            float mnew  = fmaxf(m_i[i], tm);
            float alpha = __expf(m_i[i] - mnew);
            float rs = 0.f;
            #pragma unroll
            for (int j = 0; j < 4; j++) {
                float p = __expf(s[i][j] - mnew);
                s[i][j] = p; rs += p;
            }
            #pragma unroll
            for (int mk = 8; mk; mk >>= 1)
                rs += __shfl_xor_sync(0xffffffffu, rs, mk);
            l_i[i] = l_i[i] * alpha + rs;
            m_i[i] = mnew;
            #pragma unroll
            for (int j = 0; j < 4; j++) {
                acc[i][j] *= alpha;
                Ps[ty * 8 + i][tx * 4 + j] = s[i][j];
            }
        }
        __syncthreads();

        // O += P @ V
        for (int kk = 0; kk < BK; kk++) {
            float a[8], b[4];
            #pragma unroll
            for (int i = 0; i < 8; i++) a[i] = Ps[ty * 8 + i][kk];
            #pragma unroll
            for (int j = 0; j < 4; j++) b[j] = Vs[kk][tx * 4 + j];
            #pragma unroll
            for (int i = 0; i < 8; i++)
                #pragma unroll
                for (int j = 0; j < 4; j++)
                    acc[i][j] = fmaf(a[i], b[j], acc[i][j]);
        }
        __syncthreads();
    }

    #pragma unroll
    for (int i = 0; i < 8; i++) {
        float inv = 1.f / l_i[i];
        #pragma unroll
        for (int j = 0; j < 4; j++)
            O[(size_t)(q0 + ty * 8 + i) * DIM + h * HD + tx * 4 + j] = acc[i][j] * inv;
    }
}

// ---------------------------------------------------------------------------
// Launch
// ---------------------------------------------------------------------------
extern "C" void kernel_launch(void* const* d_in, const int* in_sizes, int n_in,
                              void* d_out, int out_size)
{
    const float* hs  = (const float*)d_in[0];
    const float* ehs = (const float*)d_in[1];
    const float* Wq  = (const float*)d_in[2];
    const float* bq  = (const float*)d_in[3];
    const float* Wk  = (const float*)d_in[4];
    const float* bk  = (const float*)d_in[5];
    const float* Wv  = (const float*)d_in[6];
    const float* bv  = (const float*)d_in[7];
    const float* Waq = (const float*)d_in[8];
    const float* baq = (const float*)d_in[9];
    const float* Wak = (const float*)d_in[10];
    const float* bak = (const float*)d_in[11];
    const float* Wav = (const float*)d_in[12];
    const float* bav = (const float*)d_in[13];
    const float* Wo  = (const float*)d_in[14];
    const float* bo  = (const float*)d_in[15];
    const float* Wao = (const float*)d_in[16];
    const float* bao = (const float*)d_in[17];
    const float* gq  = (const float*)d_in[18];
    const float* gk  = (const float*)d_in[19];
    const float* gaq = (const float*)d_in[20];
    const float* gak = (const float*)d_in[21];
    float* out = (float*)d_out;

    float *qp, *kp, *vp, *op;
    cudaGetSymbolAddress((void**)&qp, g_q);
    cudaGetSymbolAddress((void**)&kp, g_k);
    cudaGetSymbolAddress((void**)&vp, g_v);
    cudaGetSymbolAddress((void**)&op, g_o);

    dim3 gH(DIM / 64, S_IMG / 128);   // (24, 16)
    dim3 gE(DIM / 64, T_TXT / 128);   // (24, 4)

    // Projections -> q_cat / k_cat / v_cat
    gemm_bias<<<gH, 256>>>(hs,  Wq,  bq,  qp);
    gemm_bias<<<gE, 256>>>(ehs, Waq, baq, qp + (size_t)S_IMG * DIM);
    gemm_bias<<<gH, 256>>>(hs,  Wk,  bk,  kp);
    gemm_bias<<<gE, 256>>>(ehs, Wak, bak, kp + (size_t)S_IMG * DIM);
    gemm_bias<<<gH, 256>>>(hs,  Wv,  bv,  vp);
    gemm_bias<<<gE, 256>>>(ehs, Wav, bav, vp + (size_t)S_IMG * DIM);

    // Per-head LayerNorm on q_cat and k_cat (in place)
    ln_heads<<<dim3(LTOT * NH / 8, 2), 256>>>(qp, kp, gq, gk, gaq, gak);

    // Attention
    cudaFuncSetAttribute(attn_kernel, cudaFuncAttributeMaxDynamicSharedMemorySize, SMEM_ATTN);
    attn_kernel<<<dim3(LTOT / BQ, NH), 256, SMEM_ATTN>>>(qp, kp, vp, op);

    // Output projections straight into d_out (img rows, then txt rows)
    gemm_bias<<<gH, 256>>>(op, Wo, bo, out);
    gemm_bias<<<gE, 256>>>(op + (size_t)S_IMG * DIM, Wao, bao, out + (size_t)S_IMG * DIM);
}

// round 6
// speedup vs baseline: 3.6831x; 3.6831x over previous
#include <cuda_runtime.h>
#include <cuda_fp16.h>
#include <cstdint>

#define DIM   1536
#define NH    24
#define HD    64
#define S_IMG 2048
#define T_TXT 512
#define LTOT  2560
#define GP    72

// ---------------- device scratch (no allocation allowed) -------------------
__device__ __half g_hshi[S_IMG * DIM], g_hslo[S_IMG * DIM];
__device__ __half g_ehi[T_TXT * DIM],  g_elo[T_TXT * DIM];
__device__ __half g_whi[8][DIM * DIM], g_wlo[8][DIM * DIM];
__device__ __half g_qhi[LTOT * DIM], g_qlo[LTOT * DIM];
__device__ __half g_khi[LTOT * DIM], g_klo[LTOT * DIM];
__device__ __half g_vhi[LTOT * DIM], g_vlo[LTOT * DIM];
__device__ __half g_ohi[LTOT * DIM], g_olo[LTOT * DIM];

// ---------------- base-ISA PTX helpers -------------------------------------
__device__ __forceinline__ uint32_t smem_u32(const void* p) {
    uint32_t a;
    asm("{ .reg .u64 t; cvta.to.shared.u64 t, %1; cvt.u32.u64 %0, t; }" : "=r"(a) : "l"(p));
    return a;
}
__device__ __forceinline__ void ldm_x4(uint32_t a, uint32_t* r) {
    asm volatile("ldmatrix.sync.aligned.m8n8.x4.shared.b16 {%0,%1,%2,%3}, [%4];"
        : "=r"(r[0]), "=r"(r[1]), "=r"(r[2]), "=r"(r[3]) : "r"(a));
}
__device__ __forceinline__ void ldm_x2(uint32_t a, uint32_t* r) {
    asm volatile("ldmatrix.sync.aligned.m8n8.x2.shared.b16 {%0,%1}, [%2];"
        : "=r"(r[0]), "=r"(r[1]) : "r"(a));
}
__device__ __forceinline__ void ldm_x2t(uint32_t a, uint32_t* r) {
    asm volatile("ldmatrix.sync.aligned.m8n8.x2.trans.shared.b16 {%0,%1}, [%2];"
        : "=r"(r[0]), "=r"(r[1]) : "r"(a));
}
__device__ __forceinline__ void mma16816(float* c, const uint32_t* a, const uint32_t* b) {
    asm volatile(
        "mma.sync.aligned.m16n8k16.row.col.f32.f16.f16.f32 "
        "{%0,%1,%2,%3}, {%4,%5,%6,%7}, {%8,%9}, {%0,%1,%2,%3};"
        : "+f"(c[0]), "+f"(c[1]), "+f"(c[2]), "+f"(c[3])
        : "r"(a[0]), "r"(a[1]), "r"(a[2]), "r"(a[3]), "r"(b[0]), "r"(b[1]));
}
__device__ __forceinline__ void cpa16(uint32_t d, const void* g) {
    asm volatile("cp.async.cg.shared.global [%0], [%1], 16;" :: "r"(d), "l"(g));
}
#define CP_COMMIT() asm volatile("cp.async.commit_group;" ::: "memory")
#define CP_WAIT1()  asm volatile("cp.async.wait_group 1;" ::: "memory")
#define CP_WAIT0()  asm volatile("cp.async.wait_group 0;" ::: "memory")

// ---------------------------------------------------------------------------
// fp32 -> (hi, lo) fp16 split
// ---------------------------------------------------------------------------
__global__ __launch_bounds__(256) void cvt_split(
    const float* __restrict__ s, __half* __restrict__ hi, __half* __restrict__ lo, int n)
{
    int i = (blockIdx.x * 256 + threadIdx.x) * 4;
    if (i >= n) return;
    float4 x = *(const float4*)(s + i);
    __half h0 = __float2half_rn(x.x), h1 = __float2half_rn(x.y);
    __half h2 = __float2half_rn(x.z), h3 = __float2half_rn(x.w);
    *(__half2*)(hi + i)     = __halves2half2(h0, h1);
    *(__half2*)(hi + i + 2) = __halves2half2(h2, h3);
    *(__half2*)(lo + i)     = __halves2half2(__float2half_rn(x.x - __half2float(h0)),
                                             __float2half_rn(x.y - __half2float(h1)));
    *(__half2*)(lo + i + 2) = __halves2half2(__float2half_rn(x.z - __half2float(h2)),
                                             __float2half_rn(x.w - __half2float(h3)));
}

// ---------------------------------------------------------------------------
// Split-fp16 GEMM: Y = X @ W^T + b  (+ optional fused per-head LayerNorm)
// 128x128 tile, BK=64, cp.async double-buffered, 8 warps as 4(M)x2(N).
// blockIdx.y: 0-15 img part, 16+ txt part (rows concatenated in outputs).
// Output: fp16 hi/lo (Ohi/Olo) or fp32 (Of).
// ---------------------------------------------------------------------------
struct GArg {
    const __half* Ahi[2]; const __half* Alo[2];
    const __half* Whi[2][3]; const __half* Wlo[2][3];
    const float* bias[2][3]; const float* gamma[2][3];
    __half* Ohi[3]; __half* Olo[3]; float* Of[3];
};

#define G_T (128 * GP)
#define G_STAGE (4 * G_T)
#define GEMM_SMEM (2 * G_STAGE * 2)

__global__ __launch_bounds__(256) void gemm_split(GArg g)
{
    extern __shared__ __half sm[];
    const int tid = threadIdx.x, wid = tid >> 5, lane = tid & 31;
    const int part = blockIdx.y >= 16;
    const int arow0 = (part ? blockIdx.y - 16 : blockIdx.y) * 128;
    const int mOut = blockIdx.y * 128;
    const int z = blockIdx.z;
    const int n0 = blockIdx.x * 128;
    const __half* Ah = g.Ahi[part]; const __half* Al = g.Alo[part];
    const __half* Wh = g.Whi[part][z]; const __half* Wl = g.Wlo[part][z];
    const uint32_t sb0 = smem_u32(sm);

    auto load_stage = [&](int s, int k0) {
        uint32_t base = sb0 + (uint32_t)s * G_STAGE * 2;
        #pragma unroll
        for (int t = 0; t < 4; t++) {
            const __half* src = (t == 0) ? Ah : (t == 1) ? Al : (t == 2) ? Wh : Wl;
            const int rb = (t < 2) ? arow0 : n0;
            #pragma unroll
            for (int it = 0; it < 4; it++) {
                int idx = tid + it * 256;
                int row = idx >> 3, seg = idx & 7;
                cpa16(base + (uint32_t)(t * G_T + row * GP + seg * 8) * 2,
                      src + (size_t)(rb + row) * DIM + k0 + seg * 8);
            }
        }
        CP_COMMIT();
    };

    float C[2][8][4];
    #pragma unroll
    for (int a = 0; a < 2; a++)
        #pragma unroll
        for (int b = 0; b < 8; b++)
            #pragma unroll
            for (int c = 0; c < 4; c++) C[a][b][c] = 0.f;

    const int wm = (wid & 3) * 32;
    const int wn = (wid >> 2) * 64;

    load_stage(0, 0);
    for (int kc = 0; kc < 24; kc++) {
        if (kc + 1 < 24) { load_stage((kc + 1) & 1, (kc + 1) * 64); CP_WAIT1(); }
        else CP_WAIT0();
        __syncthreads();
        uint32_t sb = sb0 + (uint32_t)(kc & 1) * G_STAGE * 2;
        #pragma unroll
        for (int ks = 0; ks < 4; ks++) {
            uint32_t ah[2][4], al[2][4];
            #pragma unroll
            for (int mt = 0; mt < 2; mt++) {
                uint32_t a = sb + (uint32_t)((wm + mt * 16 + (lane & 15)) * GP
                                             + ks * 16 + (lane >> 4) * 8) * 2;
                ldm_x4(a, ah[mt]);
                ldm_x4(a + G_T * 2, al[mt]);
            }
            #pragma unroll
            for (int nt = 0; nt < 8; nt++) {
                uint32_t bh[2], bl[2];
                uint32_t b = sb + (uint32_t)(2 * G_T + (wn + nt * 8 + (lane & 7)) * GP
                                             + ks * 16 + ((lane >> 3) & 1) * 8) * 2;
                ldm_x2(b, bh);
                ldm_x2(b + G_T * 2, bl);
                #pragma unroll
                for (int mt = 0; mt < 2; mt++) {
                    mma16816(C[mt][nt], ah[mt], bh);
                    mma16816(C[mt][nt], al[mt], bh);
                    mma16816(C[mt][nt], ah[mt], bl);
                }
            }
        }
        __syncthreads();
    }

    const float* bias = g.bias[part][z];
    const float* gam  = g.gamma[part][z];
    __half* Oh = g.Ohi[z]; __half* Ol = g.Olo[z]; float* Of = g.Of[z];

    #pragma unroll
    for (int mt = 0; mt < 2; mt++)
        #pragma unroll
        for (int hf = 0; hf < 2; hf++) {
            const int row = mOut + wm + mt * 16 + (lane >> 2) + hf * 8;
            float v[16];
            #pragma unroll
            for (int nt = 0; nt < 8; nt++)
                #pragma unroll
                for (int j = 0; j < 2; j++)
                    v[nt * 2 + j] = C[mt][nt][hf * 2 + j]
                                  + bias[n0 + wn + nt * 8 + (lane & 3) * 2 + j];
            if (gam) {
                float s1 = 0.f, s2 = 0.f;
                #pragma unroll
                for (int c = 0; c < 16; c++) { s1 += v[c]; s2 += v[c] * v[c]; }
                s1 += __shfl_xor_sync(0xffffffffu, s1, 1);
                s2 += __shfl_xor_sync(0xffffffffu, s2, 1);
                s1 += __shfl_xor_sync(0xffffffffu, s1, 2);
                s2 += __shfl_xor_sync(0xffffffffu, s2, 2);
                float mean = s1 * (1.f / 64);
                float var = s2 * (1.f / 64) - mean * mean;
                float inv = rsqrtf(var + 1e-5f);
                #pragma unroll
                for (int nt = 0; nt < 8; nt++)
                    #pragma unroll
                    for (int j = 0; j < 2; j++) {
                        int c = nt * 2 + j;
                        v[c] = (v[c] - mean) * inv * gam[nt * 8 + (lane & 3) * 2 + j];
                    }
            }
            if (Oh) {
                #pragma unroll
                for (int nt = 0; nt < 8; nt++) {
                    int col = n0 + wn + nt * 8 + (lane & 3) * 2;
                    __half h0 = __float2half_rn(v[nt * 2]);
                    __half h1 = __float2half_rn(v[nt * 2 + 1]);
                    *(__half2*)(Oh + (size_t)row * DIM + col) = __halves2half2(h0, h1);
                    *(__half2*)(Ol + (size_t)row * DIM + col) = __halves2half2(
                        __float2half_rn(v[nt * 2] - __half2float(h0)),
                        __float2half_rn(v[nt * 2 + 1] - __half2float(h1)));
                }
            } else {
                #pragma unroll
                for (int nt = 0; nt < 8; nt++) {
                    int col = n0 + wn + nt * 8 + (lane & 3) * 2;
                    *(float2*)(Of + (size_t)row * DIM + col) =
                        make_float2(v[nt * 2], v[nt * 2 + 1]);
                }
            }
        }
}

// ---------------------------------------------------------------------------
// mma flash attention. 256 threads = 8 warps, each warp 16 q-rows (BQ=128).
// K-tiles of 64 keys, hi/lo K and V cp.async double-buffered.
// S = qh*kh + ql*kh + qh*kl ; O += P*vh + P*vl (P fp16 from fp32).
// ---------------------------------------------------------------------------
#define A_T (64 * GP)
#define A_STAGE (4 * A_T)
#define ATT_SMEM (2 * A_STAGE * 2)

__global__ __launch_bounds__(256) void attn_mma(
    const __half* __restrict__ Qh, const __half* __restrict__ Ql,
    const __half* __restrict__ Kh, const __half* __restrict__ Kl,
    const __half* __restrict__ Vh, const __half* __restrict__ Vl,
    __half* __restrict__ Oh, __half* __restrict__ Ol)
{
    extern __shared__ __half sm[];
    const int tid = threadIdx.x, wid = tid >> 5, lane = tid & 31;
    const int h = blockIdx.y;
    const int q0 = blockIdx.x * 128;
    const uint32_t sb0 = smem_u32(sm);
    const int hc = h * HD;

    // Stage Q (hi/lo) into stage-0 region, ldmatrix into registers.
    #pragma unroll
    for (int t = 0; t < 2; t++) {
        const __half* src = t ? Ql : Qh;
        #pragma unroll
        for (int it = 0; it < 4; it++) {
            int idx = tid + it * 256;
            int row = idx >> 3, seg = idx & 7;
            cpa16(sb0 + (uint32_t)(t * G_T + row * GP + seg * 8) * 2,
                  src + (size_t)(q0 + row) * DIM + hc + seg * 8);
        }
    }
    CP_COMMIT(); CP_WAIT0();
    __syncthreads();

    uint32_t qh[4][4], ql[4][4];
    #pragma unroll
    for (int ks = 0; ks < 4; ks++) {
        uint32_t a = sb0 + (uint32_t)((wid * 16 + (lane & 15)) * GP
                                      + ks * 16 + (lane >> 4) * 8) * 2;
        ldm_x4(a, qh[ks]);
        ldm_x4(a + G_T * 2, ql[ks]);
    }
    __syncthreads();

    auto load_kv = [&](int s, int k0) {
        uint32_t base = sb0 + (uint32_t)s * A_STAGE * 2;
        #pragma unroll
        for (int t = 0; t < 4; t++) {
            const __half* src = (t == 0) ? Kh : (t == 1) ? Kl : (t == 2) ? Vh : Vl;
            int idx = tid + (t & 1) * 256;      // 2 tensors per 512 "slots"
            // each tensor: 64 rows x 8 segs = 512 loads; 256 threads -> 2 per thread
            #pragma unroll
            for (int it = 0; it < 2; it++) {
                int id2 = tid + it * 256;
                int row = id2 >> 3, seg = id2 & 7;
                cpa16(base + (uint32_t)(t * A_T + row * GP + seg * 8) * 2,
                      src + (size_t)(k0 + row) * DIM + hc + seg * 8);
            }
            (void)idx;
        }
        CP_COMMIT();
    };

    float m_i[2] = {-1e30f, -1e30f}, l_i[2] = {0.f, 0.f};
    float O[8][4];
    #pragma unroll
    for (int d = 0; d < 8; d++)
        #pragma unroll
        for (int c = 0; c < 4; c++) O[d][c] = 0.f;

    load_kv(0, 0);
    for (int kt = 0; kt < LTOT / 64; kt++) {
        if (kt + 1 < LTOT / 64) { load_kv((kt + 1) & 1, (kt + 1) * 64); CP_WAIT1(); }
        else CP_WAIT0();
        __syncthreads();
        uint32_t kb = sb0 + (uint32_t)(kt & 1) * A_STAGE * 2;

        float S[8][4];
        #pragma unroll
        for (int nt = 0; nt < 8; nt++)
            #pragma unroll
            for (int c = 0; c < 4; c++) S[nt][c] = 0.f;

        #pragma unroll
        for (int ks = 0; ks < 4; ks++)
            #pragma unroll
            for (int nt = 0; nt < 8; nt++) {
                uint32_t bh[2], bl[2];
                uint32_t b = kb + (uint32_t)((nt * 8 + (lane & 7)) * GP
                                             + ks * 16 + ((lane >> 3) & 1) * 8) * 2;
                ldm_x2(b, bh);
                ldm_x2(b + A_T * 2, bl);
                mma16816(S[nt], qh[ks], bh);
                mma16816(S[nt], ql[ks], bh);
                mma16816(S[nt], qh[ks], bl);
            }

        // online softmax (rows: hf=0 -> lane/4, hf=1 -> lane/4+8; quad-shared)
        uint32_t pa[4][4];
        #pragma unroll
        for (int hf = 0; hf < 2; hf++) {
            float tm = -1e30f;
            #pragma unroll
            for (int nt = 0; nt < 8; nt++)
                #pragma unroll
                for (int j = 0; j < 2; j++) {
                    S[nt][hf * 2 + j] *= 0.125f;
                    tm = fmaxf(tm, S[nt][hf * 2 + j]);
                }
            tm = fmaxf(tm, __shfl_xor_sync(0xffffffffu, tm, 1));
            tm = fmaxf(tm, __shfl_xor_sync(0xffffffffu, tm, 2));
            float mnew = fmaxf(m_i[hf], tm);
            float alpha = __expf(m_i[hf] - mnew);
            float rs = 0.f;
            #pragma unroll
            for (int nt = 0; nt < 8; nt++)
                #pragma unroll
                for (int j = 0; j < 2; j++) {
                    float p = __expf(S[nt][hf * 2 + j] - mnew);
                    S[nt][hf * 2 + j] = p;
                    rs += p;
                }
            rs += __shfl_xor_sync(0xffffffffu, rs, 1);
            rs += __shfl_xor_sync(0xffffffffu, rs, 2);
            l_i[hf] = l_i[hf] * alpha + rs;
            m_i[hf] = mnew;
            #pragma unroll
            for (int d = 0; d < 8; d++)
                #pragma unroll
                for (int j = 0; j < 2; j++) O[d][hf * 2 + j] *= alpha;
        }
        #pragma unroll
        for (int ks = 0; ks < 4; ks++) {
            __half2 p0 = __floats2half2_rn(S[2 * ks][0], S[2 * ks][1]);
            __half2 p1 = __floats2half2_rn(S[2 * ks][2], S[2 * ks][3]);
            __half2 p2 = __floats2half2_rn(S[2 * ks + 1][0], S[2 * ks + 1][1]);
            __half2 p3 = __floats2half2_rn(S[2 * ks + 1][2], S[2 * ks + 1][3]);
            pa[ks][0] = *(uint32_t*)&p0; pa[ks][1] = *(uint32_t*)&p1;
            pa[ks][2] = *(uint32_t*)&p2; pa[ks][3] = *(uint32_t*)&p3;
        }

        // O += P @ V (V via trans ldmatrix)
        #pragma unroll
        for (int ks = 0; ks < 4; ks++)
            #pragma unroll
            for (int dt = 0; dt < 8; dt++) {
                uint32_t bh[2], bl[2];
                uint32_t b = kb + (uint32_t)(2 * A_T + (ks * 16 + (lane & 15)) * GP
                                             + dt * 8) * 2;
                ldm_x2t(b, bh);
                ldm_x2t(b + A_T * 2, bl);
                mma16816(O[dt], pa[ks], bh);
                mma16816(O[dt], pa[ks], bl);
            }
        __syncthreads();
    }

    #pragma unroll
    for (int hf = 0; hf < 2; hf++) {
        float inv = 1.f / l_i[hf];
        int row = q0 + wid * 16 + (lane >> 2) + hf * 8;
        #pragma unroll
        for (int dt = 0; dt < 8; dt++) {
            float v0 = O[dt][hf * 2] * inv, v1 = O[dt][hf * 2 + 1] * inv;
            int col = hc + dt * 8 + (lane & 3) * 2;
            __half h0 = __float2half_rn(v0), h1 = __float2half_rn(v1);
            *(__half2*)(Oh + (size_t)row * DIM + col) = __halves2half2(h0, h1);
            *(__half2*)(Ol + (size_t)row * DIM + col) = __halves2half2(
                __float2half_rn(v0 - __half2float(h0)),
                __float2half_rn(v1 - __half2float(h1)));
        }
    }
}

// ---------------------------------------------------------------------------
// Launch
// ---------------------------------------------------------------------------
static inline void cvt_launch(const float* s, __half* hi, __half* lo, int n) {
    cvt_split<<<(n / 4 + 255) / 256, 256>>>(s, hi, lo, n);
}

extern "C" void kernel_launch(void* const* d_in, const int* in_sizes, int n_in,
                              void* d_out, int out_size)
{
    const float* hs  = (const float*)d_in[0];
    const float* ehs = (const float*)d_in[1];
    const float* Wq  = (const float*)d_in[2];
    const float* bq  = (const float*)d_in[3];
    const float* Wk  = (const float*)d_in[4];
    const float* bk  = (const float*)d_in[5];
    const float* Wv  = (const float*)d_in[6];
    const float* bv  = (const float*)d_in[7];
    const float* Waq = (const float*)d_in[8];
    const float* baq = (const float*)d_in[9];
    const float* Wak = (const float*)d_in[10];
    const float* bak = (const float*)d_in[11];
    const float* Wav = (const float*)d_in[12];
    const float* bav = (const float*)d_in[13];
    const float* Wo  = (const float*)d_in[14];
    const float* bo  = (const float*)d_in[15];
    const float* Wao = (const float*)d_in[16];
    const float* bao = (const float*)d_in[17];
    const float* gq  = (const float*)d_in[18];
    const float* gk  = (const float*)d_in[19];
    const float* gaq = (const float*)d_in[20];
    const float* gak = (const float*)d_in[21];
    float* out = (float*)d_out;

    __half *hshi, *hslo, *ehi, *elo, *whi, *wlo;
    __half *qhi, *qlo, *khi, *klo, *vhi, *vlo, *ohi, *olo;
    cudaGetSymbolAddress((void**)&hshi, g_hshi);
    cudaGetSymbolAddress((void**)&hslo, g_hslo);
    cudaGetSymbolAddress((void**)&ehi, g_ehi);
    cudaGetSymbolAddress((void**)&elo, g_elo);
    cudaGetSymbolAddress((void**)&whi, g_whi);
    cudaGetSymbolAddress((void**)&wlo, g_wlo);
    cudaGetSymbolAddress((void**)&qhi, g_qhi);
    cudaGetSymbolAddress((void**)&qlo, g_qlo);
    cudaGetSymbolAddress((void**)&khi, g_khi);
    cudaGetSymbolAddress((void**)&klo, g_klo);
    cudaGetSymbolAddress((void**)&vhi, g_vhi);
    cudaGetSymbolAddress((void**)&vlo, g_vlo);
    cudaGetSymbolAddress((void**)&ohi, g_ohi);
    cudaGetSymbolAddress((void**)&olo, g_olo);

    const float* Ws[8] = {Wq, Wk, Wv, Waq, Wak, Wav, Wo, Wao};
    __half* wh[8]; __half* wl[8];
    for (int i = 0; i < 8; i++) {
        wh[i] = whi + (size_t)i * DIM * DIM;
        wl[i] = wlo + (size_t)i * DIM * DIM;
        cvt_launch(Ws[i], wh[i], wl[i], DIM * DIM);
    }
    cvt_launch(hs,  hshi, hslo, S_IMG * DIM);
    cvt_launch(ehs, ehi,  elo,  T_TXT * DIM);

    cudaFuncSetAttribute(gemm_split, cudaFuncAttributeMaxDynamicSharedMemorySize, GEMM_SMEM);
    cudaFuncSetAttribute(attn_mma, cudaFuncAttributeMaxDynamicSharedMemorySize, ATT_SMEM);

    // Projections: one launch, z = {q,k,v}, y = 20 row-blocks (img|txt)
    GArg pa;
    pa.Ahi[0] = hshi; pa.Alo[0] = hslo; pa.Ahi[1] = ehi; pa.Alo[1] = elo;
    pa.Whi[0][0] = wh[0]; pa.Whi[0][1] = wh[1]; pa.Whi[0][2] = wh[2];
    pa.Wlo[0][0] = wl[0]; pa.Wlo[0][1] = wl[1]; pa.Wlo[0][2] = wl[2];
    pa.Whi[1][0] = wh[3]; pa.Whi[1][1] = wh[4]; pa.Whi[1][2] = wh[5];
    pa.Wlo[1][0] = wl[3]; pa.Wlo[1][1] = wl[4]; pa.Wlo[1][2] = wl[5];
    pa.bias[0][0] = bq;  pa.bias[0][1] = bk;  pa.bias[0][2] = bv;
    pa.bias[1][0] = baq; pa.bias[1][1] = bak; pa.bias[1][2] = bav;
    pa.gamma[0][0] = gq;  pa.gamma[0][1] = gk;  pa.gamma[0][2] = nullptr;
    pa.gamma[1][0] = gaq; pa.gamma[1][1] = gak; pa.gamma[1][2] = nullptr;
    pa.Ohi[0] = qhi; pa.Ohi[1] = khi; pa.Ohi[2] = vhi;
    pa.Olo[0] = qlo; pa.Olo[1] = klo; pa.Olo[2] = vlo;
    pa.Of[0] = pa.Of[1] = pa.Of[2] = nullptr;
    gemm_split<<<dim3(DIM / 128, LTOT / 128, 3), 256, GEMM_SMEM>>>(pa);

    // Attention
    attn_mma<<<dim3(LTOT / 128, NH), 256, ATT_SMEM>>>(
        qhi, qlo, khi, klo, vhi, vlo, ohi, olo);

    // Output projection straight into d_out (rows already concatenated)
    GArg po;
    po.Ahi[0] = ohi; po.Alo[0] = olo;
    po.Ahi[1] = ohi + (size_t)S_IMG * DIM; po.Alo[1] = olo + (size_t)S_IMG * DIM;
    po.Whi[0][0] = wh[6]; po.Wlo[0][0] = wl[6];
    po.Whi[1][0] = wh[7]; po.Wlo[1][0] = wl[7];
    po.Whi[0][1] = po.Whi[0][2] = po.Whi[1][1] = po.Whi[1][2] = nullptr;
    po.Wlo[0][1] = po.Wlo[0][2] = po.Wlo[1][1] = po.Wlo[1][2] = nullptr;
    po.bias[0][0] = bo; po.bias[1][0] = bao;
    po.bias[0][1] = po.bias[0][2] = po.bias[1][1] = po.bias[1][2] = nullptr;
    po.gamma[0][0] = po.gamma[0][1] = po.gamma[0][2] = nullptr;
    po.gamma[1][0] = po.gamma[1][1] = po.gamma[1][2] = nullptr;
    po.Ohi[0] = po.Ohi[1] = po.Ohi[2] = nullptr;
    po.Olo[0] = po.Olo[1] = po.Olo[2] = nullptr;
    po.Of[0] = out; po.Of[1] = po.Of[2] = nullptr;
    gemm_split<<<dim3(DIM / 128, LTOT / 128, 1), 256, GEMM_SMEM>>>(po);
}

// round 9
// speedup vs baseline: 4.5368x; 1.2318x over previous
#include <cuda_runtime.h>
#include <cuda_fp16.h>
#include <cstdint>

#define DIM   1536
#define NH    24
#define HD    64
#define S_IMG 2048
#define T_TXT 512
#define LTOT  2560
#define GP    72

// ---------------- device scratch (no allocation allowed) -------------------
__device__ __half g_hshi[S_IMG * DIM], g_hslo[S_IMG * DIM];
__device__ __half g_ehi[T_TXT * DIM],  g_elo[T_TXT * DIM];
__device__ __half g_whi[8][DIM * DIM];
__device__ __half g_qhi[LTOT * DIM], g_qlo[LTOT * DIM];
__device__ __half g_khi[LTOT * DIM];
__device__ __half g_vhi[LTOT * DIM], g_vlo[LTOT * DIM];
__device__ __half g_ohi[LTOT * DIM], g_olo[LTOT * DIM];

// ---------------- base-ISA PTX helpers -------------------------------------
__device__ __forceinline__ uint32_t smem_u32(const void* p) {
    uint32_t a;
    asm("{ .reg .u64 t; cvta.to.shared.u64 t, %1; cvt.u32.u64 %0, t; }" : "=r"(a) : "l"(p));
    return a;
}
__device__ __forceinline__ void ldm_x4(uint32_t a, uint32_t* r) {
    asm volatile("ldmatrix.sync.aligned.m8n8.x4.shared.b16 {%0,%1,%2,%3}, [%4];"
        : "=r"(r[0]), "=r"(r[1]), "=r"(r[2]), "=r"(r[3]) : "r"(a));
}
__device__ __forceinline__ void ldm_x2(uint32_t a, uint32_t* r) {
    asm volatile("ldmatrix.sync.aligned.m8n8.x2.shared.b16 {%0,%1}, [%2];"
        : "=r"(r[0]), "=r"(r[1]) : "r"(a));
}
__device__ __forceinline__ void ldm_x2t(uint32_t a, uint32_t* r) {
    asm volatile("ldmatrix.sync.aligned.m8n8.x2.trans.shared.b16 {%0,%1}, [%2];"
        : "=r"(r[0]), "=r"(r[1]) : "r"(a));
}
__device__ __forceinline__ void mma16816(float* c, const uint32_t* a, const uint32_t* b) {
    asm volatile(
        "mma.sync.aligned.m16n8k16.row.col.f32.f16.f16.f32 "
        "{%0,%1,%2,%3}, {%4,%5,%6,%7}, {%8,%9}, {%0,%1,%2,%3};"
        : "+f"(c[0]), "+f"(c[1]), "+f"(c[2]), "+f"(c[3])
        : "r"(a[0]), "r"(a[1]), "r"(a[2]), "r"(a[3]), "r"(b[0]), "r"(b[1]));
}
__device__ __forceinline__ void cpa16(uint32_t d, const void* g) {
    asm volatile("cp.async.cg.shared.global [%0], [%1], 16;" :: "r"(d), "l"(g));
}
#define CP_COMMIT() asm volatile("cp.async.commit_group;" ::: "memory")
#define CP_WAIT1()  asm volatile("cp.async.wait_group 1;" ::: "memory")
#define CP_WAIT0()  asm volatile("cp.async.wait_group 0;" ::: "memory")

// ---------------------------------------------------------------------------
// Converts: batched hi-only (weights), and hi/lo split (activations)
// ---------------------------------------------------------------------------
struct W8 { const float* s[8]; __half* d[8]; };

__global__ __launch_bounds__(256) void cvt_hi8(W8 w) {
    const float* s = w.s[blockIdx.y];
    __half* d = w.d[blockIdx.y];
    int i = (blockIdx.x * 256 + threadIdx.x) * 8;
    float4 a = *(const float4*)(s + i);
    float4 b = *(const float4*)(s + i + 4);
    __half2 h[4];
    h[0] = __floats2half2_rn(a.x, a.y);
    h[1] = __floats2half2_rn(a.z, a.w);
    h[2] = __floats2half2_rn(b.x, b.y);
    h[3] = __floats2half2_rn(b.z, b.w);
    *(uint4*)(d + i) = *(uint4*)h;
}

__global__ __launch_bounds__(256) void cvt_split(
    const float* __restrict__ s, __half* __restrict__ hi, __half* __restrict__ lo, int n)
{
    int i = (blockIdx.x * 256 + threadIdx.x) * 4;
    if (i >= n) return;
    float4 x = *(const float4*)(s + i);
    __half h0 = __float2half_rn(x.x), h1 = __float2half_rn(x.y);
    __half h2 = __float2half_rn(x.z), h3 = __float2half_rn(x.w);
    *(__half2*)(hi + i)     = __halves2half2(h0, h1);
    *(__half2*)(hi + i + 2) = __halves2half2(h2, h3);
    *(__half2*)(lo + i)     = __halves2half2(__float2half_rn(x.x - __half2float(h0)),
                                             __float2half_rn(x.y - __half2float(h1)));
    *(__half2*)(lo + i + 2) = __halves2half2(__float2half_rn(x.z - __half2float(h2)),
                                             __float2half_rn(x.w - __half2float(h3)));
}

// ---------------------------------------------------------------------------
// 2-term split GEMM: Y = (Xhi+Xlo) @ Whi^T + b (+ optional fused per-head LN)
// 128x128 tile, BK=64, cp.async double-buffered, 8 warps as 4(M)x2(N).
// ---------------------------------------------------------------------------
struct GArg {
    const __half* Ahi[2]; const __half* Alo[2];
    const __half* Whi[2][3];
    const float* bias[2][3]; const float* gamma[2][3];
    __half* Ohi[3]; __half* Olo[3]; float* Of[3];
};

#define G_T (128 * GP)
#define G_STAGE (3 * G_T)
#define GEMM_SMEM (2 * G_STAGE * 2)

__global__ __launch_bounds__(256) void gemm_split(GArg g)
{
    extern __shared__ __half sm[];
    const int tid = threadIdx.x, wid = tid >> 5, lane = tid & 31;
    const int part = blockIdx.y >= 16;
    const int arow0 = (part ? blockIdx.y - 16 : blockIdx.y) * 128;
    const int mOut = blockIdx.y * 128;
    const int z = blockIdx.z;
    const int n0 = blockIdx.x * 128;
    const __half* Ah = g.Ahi[part]; const __half* Al = g.Alo[part];
    const __half* Wh = g.Whi[part][z];
    const uint32_t sb0 = smem_u32(sm);

    auto load_stage = [&](int s, int k0) {
        uint32_t base = sb0 + (uint32_t)s * G_STAGE * 2;
        #pragma unroll
        for (int t = 0; t < 3; t++) {
            const __half* src = (t == 0) ? Ah : (t == 1) ? Al : Wh;
            const int rb = (t < 2) ? arow0 : n0;
            #pragma unroll
            for (int it = 0; it < 4; it++) {
                int idx = tid + it * 256;
                int row = idx >> 3, seg = idx & 7;
                cpa16(base + (uint32_t)(t * G_T + row * GP + seg * 8) * 2,
                      src + (size_t)(rb + row) * DIM + k0 + seg * 8);
            }
        }
        CP_COMMIT();
    };

    float C[2][8][4];
    #pragma unroll
    for (int a = 0; a < 2; a++)
        #pragma unroll
        for (int b = 0; b < 8; b++)
            #pragma unroll
            for (int c = 0; c < 4; c++) C[a][b][c] = 0.f;

    const int wm = (wid & 3) * 32;
    const int wn = (wid >> 2) * 64;

    load_stage(0, 0);
    for (int kc = 0; kc < 24; kc++) {
        if (kc + 1 < 24) { load_stage((kc + 1) & 1, (kc + 1) * 64); CP_WAIT1(); }
        else CP_WAIT0();
        __syncthreads();
        uint32_t sb = sb0 + (uint32_t)(kc & 1) * G_STAGE * 2;
        #pragma unroll
        for (int ks = 0; ks < 4; ks++) {
            uint32_t ah[2][4], al[2][4];
            #pragma unroll
            for (int mt = 0; mt < 2; mt++) {
                uint32_t a = sb + (uint32_t)((wm + mt * 16 + (lane & 15)) * GP
                                             + ks * 16 + (lane >> 4) * 8) * 2;
                ldm_x4(a, ah[mt]);
                ldm_x4(a + G_T * 2, al[mt]);
            }
            #pragma unroll
            for (int nt = 0; nt < 8; nt++) {
                uint32_t bh[2];
                uint32_t b = sb + (uint32_t)(2 * G_T + (wn + nt * 8 + (lane & 7)) * GP
                                             + ks * 16 + ((lane >> 3) & 1) * 8) * 2;
                ldm_x2(b, bh);
                #pragma unroll
                for (int mt = 0; mt < 2; mt++) {
                    mma16816(C[mt][nt], ah[mt], bh);
                    mma16816(C[mt][nt], al[mt], bh);
                }
            }
        }
        __syncthreads();
    }

    const float* bias = g.bias[part][z];
    const float* gam  = g.gamma[part][z];
    __half* Oh = g.Ohi[z]; __half* Ol = g.Olo[z]; float* Of = g.Of[z];

    #pragma unroll
    for (int mt = 0; mt < 2; mt++)
        #pragma unroll
        for (int hf = 0; hf < 2; hf++) {
            const int row = mOut + wm + mt * 16 + (lane >> 2) + hf * 8;
            float v[16];
            #pragma unroll
            for (int nt = 0; nt < 8; nt++)
                #pragma unroll
                for (int j = 0; j < 2; j++)
                    v[nt * 2 + j] = C[mt][nt][hf * 2 + j]
                                  + bias[n0 + wn + nt * 8 + (lane & 3) * 2 + j];
            if (gam) {
                float s1 = 0.f, s2 = 0.f;
                #pragma unroll
                for (int c = 0; c < 16; c++) { s1 += v[c]; s2 += v[c] * v[c]; }
                s1 += __shfl_xor_sync(0xffffffffu, s1, 1);
                s2 += __shfl_xor_sync(0xffffffffu, s2, 1);
                s1 += __shfl_xor_sync(0xffffffffu, s1, 2);
                s2 += __shfl_xor_sync(0xffffffffu, s2, 2);
                float mean = s1 * (1.f / 64);
                float var = s2 * (1.f / 64) - mean * mean;
                float inv = rsqrtf(var + 1e-5f);
                #pragma unroll
                for (int nt = 0; nt < 8; nt++)
                    #pragma unroll
                    for (int j = 0; j < 2; j++) {
                        int c = nt * 2 + j;
                        v[c] = (v[c] - mean) * inv * gam[nt * 8 + (lane & 3) * 2 + j];
                    }
            }
            if (Oh) {
                #pragma unroll
                for (int nt = 0; nt < 8; nt++) {
                    int col = n0 + wn + nt * 8 + (lane & 3) * 2;
                    __half h0 = __float2half_rn(v[nt * 2]);
                    __half h1 = __float2half_rn(v[nt * 2 + 1]);
                    *(__half2*)(Oh + (size_t)row * DIM + col) = __halves2half2(h0, h1);
                    if (Ol)
                        *(__half2*)(Ol + (size_t)row * DIM + col) = __halves2half2(
                            __float2half_rn(v[nt * 2] - __half2float(h0)),
                            __float2half_rn(v[nt * 2 + 1] - __half2float(h1)));
                }
            } else {
                #pragma unroll
                for (int nt = 0; nt < 8; nt++) {
                    int col = n0 + wn + nt * 8 + (lane & 3) * 2;
                    *(float2*)(Of + (size_t)row * DIM + col) =
                        make_float2(v[nt * 2], v[nt * 2 + 1]);
                }
            }
        }
}

// ---------------------------------------------------------------------------
// mma flash attention. 8 warps x 16 q-rows (BQ=128), K-tiles of 64.
// S = (qh+ql) @ Kh ; O += P @ (Vh+Vl), P fp16 from fp32.
// Stage tensors: Kh, Vh, Vl (3).
// ---------------------------------------------------------------------------
#define A_T (64 * GP)
#define A_STAGE (3 * A_T)
#define ATT_SMEM (2 * A_STAGE * 2)

__global__ __launch_bounds__(256) void attn_mma(
    const __half* __restrict__ Qh, const __half* __restrict__ Ql,
    const __half* __restrict__ Kh,
    const __half* __restrict__ Vh, const __half* __restrict__ Vl,
    __half* __restrict__ Oh, __half* __restrict__ Ol)
{
    extern __shared__ __half sm[];
    const int tid = threadIdx.x, wid = tid >> 5, lane = tid & 31;
    const int h = blockIdx.y;
    const int q0 = blockIdx.x * 128;
    const uint32_t sb0 = smem_u32(sm);
    const int hc = h * HD;

    // Stage Q (hi/lo: 128 rows x 64 cols each) and read fragments.
    #pragma unroll
    for (int t = 0; t < 2; t++) {
        const __half* src = t ? Ql : Qh;
        #pragma unroll
        for (int it = 0; it < 4; it++) {
            int idx = tid + it * 256;
            int row = idx >> 3, seg = idx & 7;
            cpa16(sb0 + (uint32_t)(t * G_T + row * GP + seg * 8) * 2,
                  src + (size_t)(q0 + row) * DIM + hc + seg * 8);
        }
    }
    CP_COMMIT(); CP_WAIT0();
    __syncthreads();

    uint32_t qh[4][4], ql[4][4];
    #pragma unroll
    for (int ks = 0; ks < 4; ks++) {
        uint32_t a = sb0 + (uint32_t)((wid * 16 + (lane & 15)) * GP
                                      + ks * 16 + (lane >> 4) * 8) * 2;
        ldm_x4(a, qh[ks]);
        ldm_x4(a + G_T * 2, ql[ks]);
    }
    __syncthreads();

    auto load_kv = [&](int s, int k0) {
        uint32_t base = sb0 + (uint32_t)s * A_STAGE * 2;
        #pragma unroll
        for (int t = 0; t < 3; t++) {
            const __half* src = (t == 0) ? Kh : (t == 1) ? Vh : Vl;
            #pragma unroll
            for (int it = 0; it < 2; it++) {
                int id2 = tid + it * 256;
                int row = id2 >> 3, seg = id2 & 7;
                cpa16(base + (uint32_t)(t * A_T + row * GP + seg * 8) * 2,
                      src + (size_t)(k0 + row) * DIM + hc + seg * 8);
            }
        }
        CP_COMMIT();
    };

    float m_i[2] = {-1e30f, -1e30f}, l_i[2] = {0.f, 0.f};
    float O[8][4];
    #pragma unroll
    for (int d = 0; d < 8; d++)
        #pragma unroll
        for (int c = 0; c < 4; c++) O[d][c] = 0.f;

    load_kv(0, 0);
    for (int kt = 0; kt < LTOT / 64; kt++) {
        if (kt + 1 < LTOT / 64) { load_kv((kt + 1) & 1, (kt + 1) * 64); CP_WAIT1(); }
        else CP_WAIT0();
        __syncthreads();
        uint32_t kb = sb0 + (uint32_t)(kt & 1) * A_STAGE * 2;

        float S[8][4];
        #pragma unroll
        for (int nt = 0; nt < 8; nt++)
            #pragma unroll
            for (int c = 0; c < 4; c++) S[nt][c] = 0.f;

        #pragma unroll
        for (int ks = 0; ks < 4; ks++)
            #pragma unroll
            for (int nt = 0; nt < 8; nt++) {
                uint32_t bh[2];
                uint32_t b = kb + (uint32_t)((nt * 8 + (lane & 7)) * GP
                                             + ks * 16 + ((lane >> 3) & 1) * 8) * 2;
                ldm_x2(b, bh);
                mma16816(S[nt], qh[ks], bh);
                mma16816(S[nt], ql[ks], bh);
            }

        uint32_t pa[4][4];
        #pragma unroll
        for (int hf = 0; hf < 2; hf++) {
            float tm = -1e30f;
            #pragma unroll
            for (int nt = 0; nt < 8; nt++)
                #pragma unroll
                for (int j = 0; j < 2; j++) {
                    S[nt][hf * 2 + j] *= 0.125f;
                    tm = fmaxf(tm, S[nt][hf * 2 + j]);
                }
            tm = fmaxf(tm, __shfl_xor_sync(0xffffffffu, tm, 1));
            tm = fmaxf(tm, __shfl_xor_sync(0xffffffffu, tm, 2));
            float mnew = fmaxf(m_i[hf], tm);
            float alpha = __expf(m_i[hf] - mnew);
            float rs = 0.f;
            #pragma unroll
            for (int nt = 0; nt < 8; nt++)
                #pragma unroll
                for (int j = 0; j < 2; j++) {
                    float p = __expf(S[nt][hf * 2 + j] - mnew);
                    S[nt][hf * 2 + j] = p;
                    rs += p;
                }
            rs += __shfl_xor_sync(0xffffffffu, rs, 1);
            rs += __shfl_xor_sync(0xffffffffu, rs, 2);
            l_i[hf] = l_i[hf] * alpha + rs;
            m_i[hf] = mnew;
            #pragma unroll
            for (int d = 0; d < 8; d++)
                #pragma unroll
                for (int j = 0; j < 2; j++) O[d][hf * 2 + j] *= alpha;
        }
        #pragma unroll
        for (int ks = 0; ks < 4; ks++) {
            __half2 p0 = __floats2half2_rn(S[2 * ks][0], S[2 * ks][1]);
            __half2 p1 = __floats2half2_rn(S[2 * ks][2], S[2 * ks][3]);
            __half2 p2 = __floats2half2_rn(S[2 * ks + 1][0], S[2 * ks + 1][1]);
            __half2 p3 = __floats2half2_rn(S[2 * ks + 1][2], S[2 * ks + 1][3]);
            pa[ks][0] = *(uint32_t*)&p0; pa[ks][1] = *(uint32_t*)&p1;
            pa[ks][2] = *(uint32_t*)&p2; pa[ks][3] = *(uint32_t*)&p3;
        }

        #pragma unroll
        for (int ks = 0; ks < 4; ks++)
            #pragma unroll
            for (int dt = 0; dt < 8; dt++) {
                uint32_t bh[2], bl[2];
                uint32_t b = kb + (uint32_t)(A_T + (ks * 16 + (lane & 15)) * GP
                                             + dt * 8) * 2;
                ldm_x2t(b, bh);
                ldm_x2t(b + A_T * 2, bl);
                mma16816(O[dt], pa[ks], bh);
                mma16816(O[dt], pa[ks], bl);
            }
        __syncthreads();
    }

    #pragma unroll
    for (int hf = 0; hf < 2; hf++) {
        float inv = 1.f / l_i[hf];
        int row = q0 + wid * 16 + (lane >> 2) + hf * 8;
        #pragma unroll
        for (int dt = 0; dt < 8; dt++) {
            float v0 = O[dt][hf * 2] * inv, v1 = O[dt][hf * 2 + 1] * inv;
            int col = hc + dt * 8 + (lane & 3) * 2;
            __half h0 = __float2half_rn(v0), h1 = __float2half_rn(v1);
            *(__half2*)(Oh + (size_t)row * DIM + col) = __halves2half2(h0, h1);
            *(__half2*)(Ol + (size_t)row * DIM + col) = __halves2half2(
                __float2half_rn(v0 - __half2float(h0)),
                __float2half_rn(v1 - __half2float(h1)));
        }
    }
}

// ---------------------------------------------------------------------------
// Launch
// ---------------------------------------------------------------------------
extern "C" void kernel_launch(void* const* d_in, const int* in_sizes, int n_in,
                              void* d_out, int out_size)
{
    const float* hs  = (const float*)d_in[0];
    const float* ehs = (const float*)d_in[1];
    const float* Wq  = (const float*)d_in[2];
    const float* bq  = (const float*)d_in[3];
    const float* Wk  = (const float*)d_in[4];
    const float* bk  = (const float*)d_in[5];
    const float* Wv  = (const float*)d_in[6];
    const float* bv  = (const float*)d_in[7];
    const float* Waq = (const float*)d_in[8];
    const float* baq = (const float*)d_in[9];
    const float* Wak = (const float*)d_in[10];
    const float* bak = (const float*)d_in[11];
    const float* Wav = (const float*)d_in[12];
    const float* bav = (const float*)d_in[13];
    const float* Wo  = (const float*)d_in[14];
    const float* bo  = (const float*)d_in[15];
    const float* Wao = (const float*)d_in[16];
    const float* bao = (const float*)d_in[17];
    const float* gq  = (const float*)d_in[18];
    const float* gk  = (const float*)d_in[19];
    const float* gaq = (const float*)d_in[20];
    const float* gak = (const float*)d_in[21];
    float* out = (float*)d_out;

    __half *hshi, *hslo, *ehi, *elo, *whi;
    __half *qhi, *qlo, *khi, *vhi, *vlo, *ohi, *olo;
    cudaGetSymbolAddress((void**)&hshi, g_hshi);
    cudaGetSymbolAddress((void**)&hslo, g_hslo);
    cudaGetSymbolAddress((void**)&ehi, g_ehi);
    cudaGetSymbolAddress((void**)&elo, g_elo);
    cudaGetSymbolAddress((void**)&whi, g_whi);
    cudaGetSymbolAddress((void**)&qhi, g_qhi);
    cudaGetSymbolAddress((void**)&qlo, g_qlo);
    cudaGetSymbolAddress((void**)&khi, g_khi);
    cudaGetSymbolAddress((void**)&vhi, g_vhi);
    cudaGetSymbolAddress((void**)&vlo, g_vlo);
    cudaGetSymbolAddress((void**)&ohi, g_ohi);
    cudaGetSymbolAddress((void**)&olo, g_olo);

    const float* Ws[8] = {Wq, Wk, Wv, Waq, Wak, Wav, Wo, Wao};
    __half* wh[8];
    W8 wc;
    for (int i = 0; i < 8; i++) {
        wh[i] = whi + (size_t)i * DIM * DIM;
        wc.s[i] = Ws[i];
        wc.d[i] = wh[i];
    }
    cvt_hi8<<<dim3(DIM * DIM / 8 / 256, 8), 256>>>(wc);
    cvt_split<<<(S_IMG * DIM / 4 + 255) / 256, 256>>>(hs, hshi, hslo, S_IMG * DIM);
    cvt_split<<<(T_TXT * DIM / 4 + 255) / 256, 256>>>(ehs, ehi, elo, T_TXT * DIM);

    cudaFuncSetAttribute(gemm_split, cudaFuncAttributeMaxDynamicSharedMemorySize, GEMM_SMEM);
    cudaFuncSetAttribute(attn_mma, cudaFuncAttributeMaxDynamicSharedMemorySize, ATT_SMEM);

    // Projections: z = {q,k,v}; k is hi-only output, q/v hi+lo
    GArg pa;
    pa.Ahi[0] = hshi; pa.Alo[0] = hslo; pa.Ahi[1] = ehi; pa.Alo[1] = elo;
    pa.Whi[0][0] = wh[0]; pa.Whi[0][1] = wh[1]; pa.Whi[0][2] = wh[2];
    pa.Whi[1][0] = wh[3]; pa.Whi[1][1] = wh[4]; pa.Whi[1][2] = wh[5];
    pa.bias[0][0] = bq;  pa.bias[0][1] = bk;  pa.bias[0][2] = bv;
    pa.bias[1][0] = baq; pa.bias[1][1] = bak; pa.bias[1][2] = bav;
    pa.gamma[0][0] = gq;  pa.gamma[0][1] = gk;  pa.gamma[0][2] = nullptr;
    pa.gamma[1][0] = gaq; pa.gamma[1][1] = gak; pa.gamma[1][2] = nullptr;
    pa.Ohi[0] = qhi; pa.Ohi[1] = khi; pa.Ohi[2] = vhi;
    pa.Olo[0] = qlo; pa.Olo[1] = nullptr; pa.Olo[2] = vlo;
    pa.Of[0] = pa.Of[1] = pa.Of[2] = nullptr;
    gemm_split<<<dim3(DIM / 128, LTOT / 128, 3), 256, GEMM_SMEM>>>(pa);

    attn_mma<<<dim3(LTOT / 128, NH), 256, ATT_SMEM>>>(
        qhi, qlo, khi, vhi, vlo, ohi, olo);

    // Output projection straight into d_out
    GArg po;
    po.Ahi[0] = ohi; po.Alo[0] = olo;
    po.Ahi[1] = ohi + (size_t)S_IMG * DIM; po.Alo[1] = olo + (size_t)S_IMG * DIM;
    po.Whi[0][0] = wh[6]; po.Whi[1][0] = wh[7];
    po.Whi[0][1] = po.Whi[0][2] = po.Whi[1][1] = po.Whi[1][2] = nullptr;
    po.bias[0][0] = bo; po.bias[1][0] = bao;
    po.bias[0][1] = po.bias[0][2] = po.bias[1][1] = po.bias[1][2] = nullptr;
    po.gamma[0][0] = po.gamma[0][1] = po.gamma[0][2] = nullptr;
    po.gamma[1][0] = po.gamma[1][1] = po.gamma[1][2] = nullptr;
    po.Ohi[0] = po.Ohi[1] = po.Ohi[2] = nullptr;
    po.Olo[0] = po.Olo[1] = po.Olo[2] = nullptr;
    po.Of[0] = out; po.Of[1] = po.Of[2] = nullptr;
    gemm_split<<<dim3(DIM / 128, LTOT / 128, 1), 256, GEMM_SMEM>>>(po);
}

// round 10
// speedup vs baseline: 4.8445x; 1.0678x over previous
#include <cuda_runtime.h>
#include <cuda_fp16.h>
#include <cstdint>

#define DIM   1536
#define NH    24
#define HD    64
#define S_IMG 2048
#define T_TXT 512
#define LTOT  2560
#define GP    72

// ---------------- device scratch (no allocation allowed) -------------------
__device__ __half g_hshi[S_IMG * DIM], g_hslo[S_IMG * DIM];
__device__ __half g_ehi[T_TXT * DIM],  g_elo[T_TXT * DIM];
__device__ __half g_whi[8][DIM * DIM];
__device__ __half g_qhi[LTOT * DIM], g_qlo[LTOT * DIM];
__device__ __half g_khi[LTOT * DIM];
__device__ __half g_vhi[LTOT * DIM], g_vlo[LTOT * DIM];
__device__ __half g_ohi[LTOT * DIM], g_olo[LTOT * DIM];

// ---------------- base-ISA PTX helpers -------------------------------------
__device__ __forceinline__ uint32_t smem_u32(const void* p) {
    uint32_t a;
    asm("{ .reg .u64 t; cvta.to.shared.u64 t, %1; cvt.u32.u64 %0, t; }" : "=r"(a) : "l"(p));
    return a;
}
__device__ __forceinline__ void ldm_x4(uint32_t a, uint32_t* r) {
    asm volatile("ldmatrix.sync.aligned.m8n8.x4.shared.b16 {%0,%1,%2,%3}, [%4];"
        : "=r"(r[0]), "=r"(r[1]), "=r"(r[2]), "=r"(r[3]) : "r"(a));
}
__device__ __forceinline__ void ldm_x2(uint32_t a, uint32_t* r) {
    asm volatile("ldmatrix.sync.aligned.m8n8.x2.shared.b16 {%0,%1}, [%2];"
        : "=r"(r[0]), "=r"(r[1]) : "r"(a));
}
__device__ __forceinline__ void ldm_x2t(uint32_t a, uint32_t* r) {
    asm volatile("ldmatrix.sync.aligned.m8n8.x2.trans.shared.b16 {%0,%1}, [%2];"
        : "=r"(r[0]), "=r"(r[1]) : "r"(a));
}
__device__ __forceinline__ void mma16816(float* c, const uint32_t* a, const uint32_t* b) {
    asm volatile(
        "mma.sync.aligned.m16n8k16.row.col.f32.f16.f16.f32 "
        "{%0,%1,%2,%3}, {%4,%5,%6,%7}, {%8,%9}, {%0,%1,%2,%3};"
        : "+f"(c[0]), "+f"(c[1]), "+f"(c[2]), "+f"(c[3])
        : "r"(a[0]), "r"(a[1]), "r"(a[2]), "r"(a[3]), "r"(b[0]), "r"(b[1]));
}
__device__ __forceinline__ void cpa16(uint32_t d, const void* g) {
    asm volatile("cp.async.cg.shared.global [%0], [%1], 16;" :: "r"(d), "l"(g));
}
#define CP_COMMIT() asm volatile("cp.async.commit_group;" ::: "memory")
#define CP_WAIT1()  asm volatile("cp.async.wait_group 1;" ::: "memory")
#define CP_WAIT0()  asm volatile("cp.async.wait_group 0;" ::: "memory")

// ---------------------------------------------------------------------------
// Converts: batched hi-only (weights), and hi/lo split (activations)
// ---------------------------------------------------------------------------
struct W8 { const float* s[8]; __half* d[8]; };

__global__ __launch_bounds__(256) void cvt_hi8(W8 w) {
    const float* s = w.s[blockIdx.y];
    __half* d = w.d[blockIdx.y];
    int i = (blockIdx.x * 256 + threadIdx.x) * 8;
    float4 a = *(const float4*)(s + i);
    float4 b = *(const float4*)(s + i + 4);
    __half2 h[4];
    h[0] = __floats2half2_rn(a.x, a.y);
    h[1] = __floats2half2_rn(a.z, a.w);
    h[2] = __floats2half2_rn(b.x, b.y);
    h[3] = __floats2half2_rn(b.z, b.w);
    *(uint4*)(d + i) = *(uint4*)h;
}

__global__ __launch_bounds__(256) void cvt_split(
    const float* __restrict__ s, __half* __restrict__ hi, __half* __restrict__ lo, int n)
{
    int i = (blockIdx.x * 256 + threadIdx.x) * 4;
    if (i >= n) return;
    float4 x = *(const float4*)(s + i);
    __half h0 = __float2half_rn(x.x), h1 = __float2half_rn(x.y);
    __half h2 = __float2half_rn(x.z), h3 = __float2half_rn(x.w);
    *(__half2*)(hi + i)     = __halves2half2(h0, h1);
    *(__half2*)(hi + i + 2) = __halves2half2(h2, h3);
    *(__half2*)(lo + i)     = __halves2half2(__float2half_rn(x.x - __half2float(h0)),
                                             __float2half_rn(x.y - __half2float(h1)));
    *(__half2*)(lo + i + 2) = __halves2half2(__float2half_rn(x.z - __half2float(h2)),
                                             __float2half_rn(x.w - __half2float(h3)));
}

// ---------------------------------------------------------------------------
// 2-term split GEMM: Y = (Xhi+Xlo) @ Whi^T + b (+ optional fused per-head LN)
// 128x128 tile, BK=64, cp.async double-buffered, 8 warps as 4(M)x2(N).
// __launch_bounds__(256, 2): cap at 128 regs so 2 CTAs/SM fit the RF.
// ---------------------------------------------------------------------------
struct GArg {
    const __half* Ahi[2]; const __half* Alo[2];
    const __half* Whi[2][3];
    const float* bias[2][3]; const float* gamma[2][3];
    __half* Ohi[3]; __half* Olo[3]; float* Of[3];
};

#define G_T (128 * GP)
#define G_STAGE (3 * G_T)
#define GEMM_SMEM (2 * G_STAGE * 2)

__global__ __launch_bounds__(256, 2) void gemm_split(GArg g)
{
    extern __shared__ __half sm[];
    const int tid = threadIdx.x, wid = tid >> 5, lane = tid & 31;
    const int part = blockIdx.y >= 16;
    const int arow0 = (part ? blockIdx.y - 16 : blockIdx.y) * 128;
    const int mOut = blockIdx.y * 128;
    const int z = blockIdx.z;
    const int n0 = blockIdx.x * 128;
    const __half* Ah = g.Ahi[part]; const __half* Al = g.Alo[part];
    const __half* Wh = g.Whi[part][z];
    const uint32_t sb0 = smem_u32(sm);

    auto load_stage = [&](int s, int k0) {
        uint32_t base = sb0 + (uint32_t)s * G_STAGE * 2;
        #pragma unroll
        for (int t = 0; t < 3; t++) {
            const __half* src = (t == 0) ? Ah : (t == 1) ? Al : Wh;
            const int rb = (t < 2) ? arow0 : n0;
            #pragma unroll
            for (int it = 0; it < 4; it++) {
                int idx = tid + it * 256;
                int row = idx >> 3, seg = idx & 7;
                cpa16(base + (uint32_t)(t * G_T + row * GP + seg * 8) * 2,
                      src + (size_t)(rb + row) * DIM + k0 + seg * 8);
            }
        }
        CP_COMMIT();
    };

    float C[2][8][4];
    #pragma unroll
    for (int a = 0; a < 2; a++)
        #pragma unroll
        for (int b = 0; b < 8; b++)
            #pragma unroll
            for (int c = 0; c < 4; c++) C[a][b][c] = 0.f;

    const int wm = (wid & 3) * 32;
    const int wn = (wid >> 2) * 64;

    load_stage(0, 0);
    for (int kc = 0; kc < 24; kc++) {
        if (kc + 1 < 24) { load_stage((kc + 1) & 1, (kc + 1) * 64); CP_WAIT1(); }
        else CP_WAIT0();
        __syncthreads();
        uint32_t sb = sb0 + (uint32_t)(kc & 1) * G_STAGE * 2;
        #pragma unroll
        for (int ks = 0; ks < 4; ks++) {
            uint32_t ah[2][4], al[2][4];
            #pragma unroll
            for (int mt = 0; mt < 2; mt++) {
                uint32_t a = sb + (uint32_t)((wm + mt * 16 + (lane & 15)) * GP
                                             + ks * 16 + (lane >> 4) * 8) * 2;
                ldm_x4(a, ah[mt]);
                ldm_x4(a + G_T * 2, al[mt]);
            }
            #pragma unroll
            for (int nt = 0; nt < 8; nt++) {
                uint32_t bh[2];
                uint32_t b = sb + (uint32_t)(2 * G_T + (wn + nt * 8 + (lane & 7)) * GP
                                             + ks * 16 + ((lane >> 3) & 1) * 8) * 2;
                ldm_x2(b, bh);
                #pragma unroll
                for (int mt = 0; mt < 2; mt++) {
                    mma16816(C[mt][nt], ah[mt], bh);
                    mma16816(C[mt][nt], al[mt], bh);
                }
            }
        }
        __syncthreads();
    }

    const float* bias = g.bias[part][z];
    const float* gam  = g.gamma[part][z];
    __half* Oh = g.Ohi[z]; __half* Ol = g.Olo[z]; float* Of = g.Of[z];

    #pragma unroll
    for (int mt = 0; mt < 2; mt++)
        #pragma unroll
        for (int hf = 0; hf < 2; hf++) {
            const int row = mOut + wm + mt * 16 + (lane >> 2) + hf * 8;
            float v[16];
            #pragma unroll
            for (int nt = 0; nt < 8; nt++)
                #pragma unroll
                for (int j = 0; j < 2; j++)
                    v[nt * 2 + j] = C[mt][nt][hf * 2 + j]
                                  + bias[n0 + wn + nt * 8 + (lane & 3) * 2 + j];
            if (gam) {
                float s1 = 0.f, s2 = 0.f;
                #pragma unroll
                for (int c = 0; c < 16; c++) { s1 += v[c]; s2 += v[c] * v[c]; }
                s1 += __shfl_xor_sync(0xffffffffu, s1, 1);
                s2 += __shfl_xor_sync(0xffffffffu, s2, 1);
                s1 += __shfl_xor_sync(0xffffffffu, s1, 2);
                s2 += __shfl_xor_sync(0xffffffffu, s2, 2);
                float mean = s1 * (1.f / 64);
                float var = s2 * (1.f / 64) - mean * mean;
                float inv = rsqrtf(var + 1e-5f);
                #pragma unroll
                for (int nt = 0; nt < 8; nt++)
                    #pragma unroll
                    for (int j = 0; j < 2; j++) {
                        int c = nt * 2 + j;
                        v[c] = (v[c] - mean) * inv * gam[nt * 8 + (lane & 3) * 2 + j];
                    }
            }
            if (Oh) {
                #pragma unroll
                for (int nt = 0; nt < 8; nt++) {
                    int col = n0 + wn + nt * 8 + (lane & 3) * 2;
                    __half h0 = __float2half_rn(v[nt * 2]);
                    __half h1 = __float2half_rn(v[nt * 2 + 1]);
                    *(__half2*)(Oh + (size_t)row * DIM + col) = __halves2half2(h0, h1);
                    if (Ol)
                        *(__half2*)(Ol + (size_t)row * DIM + col) = __halves2half2(
                            __float2half_rn(v[nt * 2] - __half2float(h0)),
                            __float2half_rn(v[nt * 2 + 1] - __half2float(h1)));
                }
            } else {
                #pragma unroll
                for (int nt = 0; nt < 8; nt++) {
                    int col = n0 + wn + nt * 8 + (lane & 3) * 2;
                    *(float2*)(Of + (size_t)row * DIM + col) =
                        make_float2(v[nt * 2], v[nt * 2 + 1]);
                }
            }
        }
}

// ---------------------------------------------------------------------------
// mma flash attention. 8 warps x 16 q-rows (BQ=128), K-tiles of 64.
// S = (qh+ql) @ Kh ; O += P @ (Vh+Vl), P fp16 from fp32.
// __launch_bounds__(256, 2): cap regs at 128 for 2 CTAs/SM.
// ---------------------------------------------------------------------------
#define A_T (64 * GP)
#define A_STAGE (3 * A_T)
#define ATT_SMEM (2 * A_STAGE * 2)

__global__ __launch_bounds__(256, 2) void attn_mma(
    const __half* __restrict__ Qh, const __half* __restrict__ Ql,
    const __half* __restrict__ Kh,
    const __half* __restrict__ Vh, const __half* __restrict__ Vl,
    __half* __restrict__ Oh, __half* __restrict__ Ol)
{
    extern __shared__ __half sm[];
    const int tid = threadIdx.x, wid = tid >> 5, lane = tid & 31;
    const int h = blockIdx.y;
    const int q0 = blockIdx.x * 128;
    const uint32_t sb0 = smem_u32(sm);
    const int hc = h * HD;

    // Stage Q (hi/lo: 128 rows x 64 cols each) and read fragments.
    #pragma unroll
    for (int t = 0; t < 2; t++) {
        const __half* src = t ? Ql : Qh;
        #pragma unroll
        for (int it = 0; it < 4; it++) {
            int idx = tid + it * 256;
            int row = idx >> 3, seg = idx & 7;
            cpa16(sb0 + (uint32_t)(t * G_T + row * GP + seg * 8) * 2,
                  src + (size_t)(q0 + row) * DIM + hc + seg * 8);
        }
    }
    CP_COMMIT(); CP_WAIT0();
    __syncthreads();

    uint32_t qh[4][4], ql[4][4];
    #pragma unroll
    for (int ks = 0; ks < 4; ks++) {
        uint32_t a = sb0 + (uint32_t)((wid * 16 + (lane & 15)) * GP
                                      + ks * 16 + (lane >> 4) * 8) * 2;
        ldm_x4(a, qh[ks]);
        ldm_x4(a + G_T * 2, ql[ks]);
    }
    __syncthreads();

    auto load_kv = [&](int s, int k0) {
        uint32_t base = sb0 + (uint32_t)s * A_STAGE * 2;
        #pragma unroll
        for (int t = 0; t < 3; t++) {
            const __half* src = (t == 0) ? Kh : (t == 1) ? Vh : Vl;
            #pragma unroll
            for (int it = 0; it < 2; it++) {
                int id2 = tid + it * 256;
                int row = id2 >> 3, seg = id2 & 7;
                cpa16(base + (uint32_t)(t * A_T + row * GP + seg * 8) * 2,
                      src + (size_t)(k0 + row) * DIM + hc + seg * 8);
            }
        }
        CP_COMMIT();
    };

    float m_i[2] = {-1e30f, -1e30f}, l_i[2] = {0.f, 0.f};
    float O[8][4];
    #pragma unroll
    for (int d = 0; d < 8; d++)
        #pragma unroll
        for (int c = 0; c < 4; c++) O[d][c] = 0.f;

    load_kv(0, 0);
    for (int kt = 0; kt < LTOT / 64; kt++) {
        if (kt + 1 < LTOT / 64) { load_kv((kt + 1) & 1, (kt + 1) * 64); CP_WAIT1(); }
        else CP_WAIT0();
        __syncthreads();
        uint32_t kb = sb0 + (uint32_t)(kt & 1) * A_STAGE * 2;

        float S[8][4];
        #pragma unroll
        for (int nt = 0; nt < 8; nt++)
            #pragma unroll
            for (int c = 0; c < 4; c++) S[nt][c] = 0.f;

        #pragma unroll
        for (int ks = 0; ks < 4; ks++)
            #pragma unroll
            for (int nt = 0; nt < 8; nt++) {
                uint32_t bh[2];
                uint32_t b = kb + (uint32_t)((nt * 8 + (lane & 7)) * GP
                                             + ks * 16 + ((lane >> 3) & 1) * 8) * 2;
                ldm_x2(b, bh);
                mma16816(S[nt], qh[ks], bh);
                mma16816(S[nt], ql[ks], bh);
            }

        uint32_t pa[4][4];
        #pragma unroll
        for (int hf = 0; hf < 2; hf++) {
            float tm = -1e30f;
            #pragma unroll
            for (int nt = 0; nt < 8; nt++)
                #pragma unroll
                for (int j = 0; j < 2; j++) {
                    S[nt][hf * 2 + j] *= 0.125f;
                    tm = fmaxf(tm, S[nt][hf * 2 + j]);
                }
            tm = fmaxf(tm, __shfl_xor_sync(0xffffffffu, tm, 1));
            tm = fmaxf(tm, __shfl_xor_sync(0xffffffffu, tm, 2));
            float mnew = fmaxf(m_i[hf], tm);
            float alpha = __expf(m_i[hf] - mnew);
            float rs = 0.f;
            #pragma unroll
            for (int nt = 0; nt < 8; nt++)
                #pragma unroll
                for (int j = 0; j < 2; j++) {
                    float p = __expf(S[nt][hf * 2 + j] - mnew);
                    S[nt][hf * 2 + j] = p;
                    rs += p;
                }
            rs += __shfl_xor_sync(0xffffffffu, rs, 1);
            rs += __shfl_xor_sync(0xffffffffu, rs, 2);
            l_i[hf] = l_i[hf] * alpha + rs;
            m_i[hf] = mnew;
            #pragma unroll
            for (int d = 0; d < 8; d++)
                #pragma unroll
                for (int j = 0; j < 2; j++) O[d][hf * 2 + j] *= alpha;
        }
        #pragma unroll
        for (int ks = 0; ks < 4; ks++) {
            __half2 p0 = __floats2half2_rn(S[2 * ks][0], S[2 * ks][1]);
            __half2 p1 = __floats2half2_rn(S[2 * ks][2], S[2 * ks][3]);
            __half2 p2 = __floats2half2_rn(S[2 * ks + 1][0], S[2 * ks + 1][1]);
            __half2 p3 = __floats2half2_rn(S[2 * ks + 1][2], S[2 * ks + 1][3]);
            pa[ks][0] = *(uint32_t*)&p0; pa[ks][1] = *(uint32_t*)&p1;
            pa[ks][2] = *(uint32_t*)&p2; pa[ks][3] = *(uint32_t*)&p3;
        }

        #pragma unroll
        for (int ks = 0; ks < 4; ks++)
            #pragma unroll
            for (int dt = 0; dt < 8; dt++) {
                uint32_t bh[2], bl[2];
                uint32_t b = kb + (uint32_t)(A_T + (ks * 16 + (lane & 15)) * GP
                                             + dt * 8) * 2;
                ldm_x2t(b, bh);
                ldm_x2t(b + A_T * 2, bl);
                mma16816(O[dt], pa[ks], bh);
                mma16816(O[dt], pa[ks], bl);
            }
        __syncthreads();
    }

    #pragma unroll
    for (int hf = 0; hf < 2; hf++) {
        float inv = 1.f / l_i[hf];
        int row = q0 + wid * 16 + (lane >> 2) + hf * 8;
        #pragma unroll
        for (int dt = 0; dt < 8; dt++) {
            float v0 = O[dt][hf * 2] * inv, v1 = O[dt][hf * 2 + 1] * inv;
            int col = hc + dt * 8 + (lane & 3) * 2;
            __half h0 = __float2half_rn(v0), h1 = __float2half_rn(v1);
            *(__half2*)(Oh + (size_t)row * DIM + col) = __halves2half2(h0, h1);
            *(__half2*)(Ol + (size_t)row * DIM + col) = __halves2half2(
                __float2half_rn(v0 - __half2float(h0)),
                __float2half_rn(v1 - __half2float(h1)));
        }
    }
}

// ---------------------------------------------------------------------------
// Launch
// ---------------------------------------------------------------------------
extern "C" void kernel_launch(void* const* d_in, const int* in_sizes, int n_in,
                              void* d_out, int out_size)
{
    const float* hs  = (const float*)d_in[0];
    const float* ehs = (const float*)d_in[1];
    const float* Wq  = (const float*)d_in[2];
    const float* bq  = (const float*)d_in[3];
    const float* Wk  = (const float*)d_in[4];
    const float* bk  = (const float*)d_in[5];
    const float* Wv  = (const float*)d_in[6];
    const float* bv  = (const float*)d_in[7];
    const float* Waq = (const float*)d_in[8];
    const float* baq = (const float*)d_in[9];
    const float* Wak = (const float*)d_in[10];
    const float* bak = (const float*)d_in[11];
    const float* Wav = (const float*)d_in[12];
    const float* bav = (const float*)d_in[13];
    const float* Wo  = (const float*)d_in[14];
    const float* bo  = (const float*)d_in[15];
    const float* Wao = (const float*)d_in[16];
    const float* bao = (const float*)d_in[17];
    const float* gq  = (const float*)d_in[18];
    const float* gk  = (const float*)d_in[19];
    const float* gaq = (const float*)d_in[20];
    const float* gak = (const float*)d_in[21];
    float* out = (float*)d_out;

    __half *hshi, *hslo, *ehi, *elo, *whi;
    __half *qhi, *qlo, *khi, *vhi, *vlo, *ohi, *olo;
    cudaGetSymbolAddress((void**)&hshi, g_hshi);
    cudaGetSymbolAddress((void**)&hslo, g_hslo);
    cudaGetSymbolAddress((void**)&ehi, g_ehi);
    cudaGetSymbolAddress((void**)&elo, g_elo);
    cudaGetSymbolAddress((void**)&whi, g_whi);
    cudaGetSymbolAddress((void**)&qhi, g_qhi);
    cudaGetSymbolAddress((void**)&qlo, g_qlo);
    cudaGetSymbolAddress((void**)&khi, g_khi);
    cudaGetSymbolAddress((void**)&vhi, g_vhi);
    cudaGetSymbolAddress((void**)&vlo, g_vlo);
    cudaGetSymbolAddress((void**)&ohi, g_ohi);
    cudaGetSymbolAddress((void**)&olo, g_olo);

    const float* Ws[8] = {Wq, Wk, Wv, Waq, Wak, Wav, Wo, Wao};
    __half* wh[8];
    W8 wc;
    for (int i = 0; i < 8; i++) {
        wh[i] = whi + (size_t)i * DIM * DIM;
        wc.s[i] = Ws[i];
        wc.d[i] = wh[i];
    }
    cvt_hi8<<<dim3(DIM * DIM / 8 / 256, 8), 256>>>(wc);
    cvt_split<<<(S_IMG * DIM / 4 + 255) / 256, 256>>>(hs, hshi, hslo, S_IMG * DIM);
    cvt_split<<<(T_TXT * DIM / 4 + 255) / 256, 256>>>(ehs, ehi, elo, T_TXT * DIM);

    cudaFuncSetAttribute(gemm_split, cudaFuncAttributeMaxDynamicSharedMemorySize, GEMM_SMEM);
    cudaFuncSetAttribute(attn_mma, cudaFuncAttributeMaxDynamicSharedMemorySize, ATT_SMEM);

    // Projections: z = {q,k,v}; k is hi-only output, q/v hi+lo
    GArg pa;
    pa.Ahi[0] = hshi; pa.Alo[0] = hslo; pa.Ahi[1] = ehi; pa.Alo[1] = elo;
    pa.Whi[0][0] = wh[0]; pa.Whi[0][1] = wh[1]; pa.Whi[0][2] = wh[2];
    pa.Whi[1][0] = wh[3]; pa.Whi[1][1] = wh[4]; pa.Whi[1][2] = wh[5];
    pa.bias[0][0] = bq;  pa.bias[0][1] = bk;  pa.bias[0][2] = bv;
    pa.bias[1][0] = baq; pa.bias[1][1] = bak; pa.bias[1][2] = bav;
    pa.gamma[0][0] = gq;  pa.gamma[0][1] = gk;  pa.gamma[0][2] = nullptr;
    pa.gamma[1][0] = gaq; pa.gamma[1][1] = gak; pa.gamma[1][2] = nullptr;
    pa.Ohi[0] = qhi; pa.Ohi[1] = khi; pa.Ohi[2] = vhi;
    pa.Olo[0] = qlo; pa.Olo[1] = nullptr; pa.Olo[2] = vlo;
    pa.Of[0] = pa.Of[1] = pa.Of[2] = nullptr;
    gemm_split<<<dim3(DIM / 128, LTOT / 128, 3), 256, GEMM_SMEM>>>(pa);

    attn_mma<<<dim3(LTOT / 128, NH), 256, ATT_SMEM>>>(
        qhi, qlo, khi, vhi, vlo, ohi, olo);

    // Output projection straight into d_out
    GArg po;
    po.Ahi[0] = ohi; po.Alo[0] = olo;
    po.Ahi[1] = ohi + (size_t)S_IMG * DIM; po.Alo[1] = olo + (size_t)S_IMG * DIM;
    po.Whi[0][0] = wh[6]; po.Whi[1][0] = wh[7];
    po.Whi[0][1] = po.Whi[0][2] = po.Whi[1][1] = po.Whi[1][2] = nullptr;
    po.bias[0][0] = bo; po.bias[1][0] = bao;
    po.bias[0][1] = po.bias[0][2] = po.bias[1][1] = po.bias[1][2] = nullptr;
    po.gamma[0][0] = po.gamma[0][1] = po.gamma[0][2] = nullptr;
    po.gamma[1][0] = po.gamma[1][1] = po.gamma[1][2] = nullptr;
    po.Ohi[0] = po.Ohi[1] = po.Ohi[2] = nullptr;
    po.Olo[0] = po.Olo[1] = po.Olo[2] = nullptr;
    po.Of[0] = out; po.Of[1] = po.Of[2] = nullptr;
    gemm_split<<<dim3(DIM / 128, LTOT / 128, 1), 256, GEMM_SMEM>>>(po);
}